// round 1
// baseline (speedup 1.0000x reference)
#include <cuda_runtime.h>
#include <stdint.h>

#define IN_F      768
#define HID       64
#define ROWS      32
#define THREADS   256
#define XS_STRIDE 769   // (lane*769 + r) % 32 == (lane + r) % 32 -> conflict-free
#define HS_STRIDE 65    // (lane*65 + c) % 32 == (lane + c) % 32 -> conflict-free

// Device scratch (no allocations allowed). int4 alignment so pair-loads are LDG.128.
__device__ int   g_cp1[HID + 1];
__device__ int   g_cp2[HID + 1];
__device__ int4  g_e1[4096];   // up to 8192 (r, v_bits) entries for W1 (4915 + pad)
__device__ int4  g_e2[1024];   // up to 2048 entries for W2 (409 + pad)
__device__ float g_w3[HID];

// ---------------------------------------------------------------------------
// Preprocess: COO -> CSC (per output column), deterministic order (original
// index order via ballot-prefix ranks), each column segment padded to an even
// count with (r=0, v=0) dummies so the main loop reads entry PAIRS as int4.
// Also densifies W3 into a dense [HID] vector.
// One block, 1024 threads = 32 warps, 2 columns per warp. ~2 us.
// ---------------------------------------------------------------------------
__global__ void prep_kernel(const int* __restrict__ idx1, const float* __restrict__ val1, int nnz1,
                            const int* __restrict__ idx2, const float* __restrict__ val2, int nnz2,
                            const int* __restrict__ idx3, const float* __restrict__ val3, int nnz3)
{
    __shared__ int cnt[HID];
    __shared__ int cp[HID + 1];

    const int tid  = threadIdx.x;
    const int w    = tid >> 5;
    const int lane = tid & 31;
    const unsigned FULL = 0xffffffffu;

    for (int phase = 0; phase < 2; ++phase) {
        const int*   idx = phase ? idx2 : idx1;
        const float* val = phase ? val2 : val1;
        const int    nnz = phase ? nnz2 : nnz1;
        int*  gcp = phase ? g_cp2 : g_cp1;
        int2* ge  = phase ? reinterpret_cast<int2*>(g_e2) : reinterpret_cast<int2*>(g_e1);
        const int* rows = idx;          // idx layout: [2, nnz] (rows then cols)
        const int* cols = idx + nnz;

        // ---- count entries per column (warp w owns cols 2w, 2w+1) ----
        #pragma unroll
        for (int jc = 0; jc < 2; ++jc) {
            const int c = w * 2 + jc;
            int cc = 0;
            for (int ib = 0; ib < nnz; ib += 32) {
                const int i = ib + lane;
                if (i < nnz && cols[i] == c) cc++;
            }
            #pragma unroll
            for (int o = 16; o; o >>= 1) cc += __shfl_xor_sync(FULL, cc, o);
            if (lane == 0) cnt[c] = cc;
        }
        __syncthreads();

        // ---- exclusive scan of even-padded counts ----
        if (tid == 0) {
            int acc = 0;
            for (int c = 0; c < HID; ++c) { cp[c] = acc; acc += (cnt[c] + 1) & ~1; }
            cp[HID] = acc;
        }
        __syncthreads();
        if (tid <= HID) gcp[tid] = cp[tid];

        // ---- deterministic scatter in original index order ----
        #pragma unroll
        for (int jc = 0; jc < 2; ++jc) {
            const int c = w * 2 + jc;
            const int base = cp[c];
            int run = 0;
            for (int ib = 0; ib < nnz; ib += 32) {
                const int i = ib + lane;
                const bool m = (i < nnz) && (cols[i] == c);
                const unsigned mk = __ballot_sync(FULL, m);
                if (m) {
                    const int pos = base + run + __popc(mk & ((1u << lane) - 1u));
                    ge[pos] = make_int2(rows[i], __float_as_int(val[i]));
                }
                run += __popc(mk);
            }
            if (lane == 0 && (run & 1)) ge[base + run] = make_int2(0, 0);
        }
        __syncthreads();
    }

    // ---- densify W3: out column is 0, row index selects HID slot ----
    if (tid < HID) {
        float s = 0.f;
        for (int i = 0; i < nnz3; ++i)
            if (idx3[i] == tid) s += val3[i];   // idx3[0..nnz3) = rows (hid index)
        g_w3[tid] = s;
    }
}

// ---------------------------------------------------------------------------
// Main fused kernel: 32 batch rows per block, 8 warps.
// Phase 0: stage x tile [32][768] fp32 into smem (stride 769, conflict-free).
// Phase 1: warp w computes h1 for columns 8w..8w+7 (lane = row), entries
//          loaded pairwise via broadcast LDG.128, x gathered via 128B LDS.
// Phase 2: same structure over h1 (smem, stride 65) for h2.
// Phase 3: warp 0 reduces h2 @ w3 + b3, writes 32 outputs.
// Smem for h1/h2 ALIASES the x tile (dead after phase 1) -> 98.4 KB total
// -> 2 blocks/SM -> HBM tile-load of one block overlaps compute of the other.
// ---------------------------------------------------------------------------
extern __shared__ float smem[];

__global__ __launch_bounds__(THREADS, 2)
void mlp_kernel(const float* __restrict__ x,
                const float* __restrict__ b1,
                const float* __restrict__ b2,
                const float* __restrict__ b3,
                float* __restrict__ out, int batch)
{
    float* xs  = smem;                         // [32][769]
    float* h1s = smem;                         // reuse (xs dead after layer 1)
    float* h2s = smem + ROWS * HS_STRIDE;      // disjoint from h1s

    const int tid  = threadIdx.x;
    const int w    = tid >> 5;
    const int lane = tid & 31;
    const int row0 = blockIdx.x * ROWS;

    // ---- stage x tile: consecutive threads load/store consecutive words ----
    {
        const float* xg = x + (long long)row0 * IN_F;
        const int totw = min(ROWS, batch - row0) * IN_F;
        #pragma unroll
        for (int k = tid; k < ROWS * IN_F; k += THREADS) {
            const int r = k / IN_F;
            const int c = k - r * IN_F;
            xs[r * XS_STRIDE + c] = (k < totw) ? __ldg(&xg[k]) : 0.f;
        }
    }
    __syncthreads();

    // ---- layer 1 ----
    float h[8];
    {
        const float* xr = xs + lane * XS_STRIDE;
        #pragma unroll
        for (int j = 0; j < 8; ++j) {
            const int c  = w * 8 + j;
            const int p0 = g_cp1[c] >> 1;
            const int p1 = g_cp1[c + 1] >> 1;
            float acc = 0.f;
            #pragma unroll 2
            for (int p = p0; p < p1; ++p) {
                const int4 pk = g_e1[p];                    // 2 entries, broadcast
                acc += xr[pk.x] * __int_as_float(pk.y);
                acc += xr[pk.z] * __int_as_float(pk.w);
            }
            h[j] = fmaxf(acc + __ldg(&b1[c]), 0.f);
        }
    }
    __syncthreads();                                        // all done reading xs
    #pragma unroll
    for (int j = 0; j < 8; ++j) h1s[lane * HS_STRIDE + w * 8 + j] = h[j];
    __syncthreads();

    // ---- layer 2 ----
    {
        const float* hr = h1s + lane * HS_STRIDE;
        #pragma unroll
        for (int j = 0; j < 8; ++j) {
            const int c  = w * 8 + j;
            const int p0 = g_cp2[c] >> 1;
            const int p1 = g_cp2[c + 1] >> 1;
            float acc = 0.f;
            for (int p = p0; p < p1; ++p) {
                const int4 pk = g_e2[p];
                acc += hr[pk.x] * __int_as_float(pk.y);
                acc += hr[pk.z] * __int_as_float(pk.w);
            }
            h[j] = fmaxf(acc + __ldg(&b2[c]), 0.f);
        }
    }
    __syncthreads();
    #pragma unroll
    for (int j = 0; j < 8; ++j) h2s[lane * HS_STRIDE + w * 8 + j] = h[j];
    __syncthreads();

    // ---- layer 3: warp 0, lane = row ----
    if (w == 0) {
        const float* hr = h2s + lane * HS_STRIDE;
        float acc = __ldg(&b3[0]);
        #pragma unroll
        for (int c = 0; c < HID; ++c) acc += hr[c] * g_w3[c];
        const int gr = row0 + lane;
        if (gr < batch) out[gr] = acc;
    }
}

// ---------------------------------------------------------------------------
extern "C" void kernel_launch(void* const* d_in, const int* in_sizes, int n_in,
                              void* d_out, int out_size)
{
    const float* x    = (const float*)d_in[0];
    const int*   idx1 = (const int*)  d_in[1];
    const float* val1 = (const float*)d_in[2];
    const float* b1   = (const float*)d_in[3];
    const int*   idx2 = (const int*)  d_in[4];
    const float* val2 = (const float*)d_in[5];
    const float* b2   = (const float*)d_in[6];
    const int*   idx3 = (const int*)  d_in[7];
    const float* val3 = (const float*)d_in[8];
    const float* b3   = (const float*)d_in[9];

    const int nnz1  = in_sizes[1] / 2;
    const int nnz2  = in_sizes[4] / 2;
    const int nnz3  = in_sizes[7] / 2;
    const int batch = in_sizes[0] / IN_F;

    const int smem_bytes = ROWS * XS_STRIDE * (int)sizeof(float);   // 98432
    cudaFuncSetAttribute(mlp_kernel, cudaFuncAttributeMaxDynamicSharedMemorySize, smem_bytes);

    prep_kernel<<<1, 1024>>>(idx1, val1, nnz1, idx2, val2, nnz2, idx3, val3, nnz3);

    const int blocks = (batch + ROWS - 1) / ROWS;
    mlp_kernel<<<blocks, THREADS, smem_bytes>>>(x, b1, b2, b3, (float*)d_out, batch);
}

// round 2
// speedup vs baseline: 2.0142x; 2.0142x over previous
#include <cuda_runtime.h>
#include <stdint.h>

#define IN_F      768
#define HID       64
#define ROWS      32
#define THREADS   512
#define COLS_PER_WARP 4      // 16 warps * 4 = 64 columns
#define XS_STRIDE 769        // (lane*769 + r) % 32 == (lane + r) % 32 -> conflict-free
#define HS_STRIDE 65         // (lane*65  + c) % 32 == (lane + c) % 32 -> conflict-free

// Device scratch (no allocations allowed). int4 loads give LDG.128 entry pairs.
__device__ int   g_cp1[HID + 1];
__device__ int   g_cp2[HID + 1];
__device__ int4  g_e1[4096];   // 8192 (r, v_bits) int2 entries for W1 (4915 + pad-to-8)
__device__ int4  g_e2[1024];   // 2048 entries for W2 (409 + pad-to-8)
__device__ float g_w3[HID];

// ---------------------------------------------------------------------------
// Preprocess: COO -> CSC per output column, deterministic (original index
// order via ballot-prefix ranks). Each column segment padded to a multiple of
// EIGHT entries (4 int4s) with zeros so the main loop unrolls 4x with no tail.
// Also densifies W3. One block, 1024 threads, 2 columns per warp.
// ---------------------------------------------------------------------------
__global__ void prep_kernel(const int* __restrict__ idx1, const float* __restrict__ val1, int nnz1,
                            const int* __restrict__ idx2, const float* __restrict__ val2, int nnz2,
                            const int* __restrict__ idx3, const float* __restrict__ val3, int nnz3)
{
    __shared__ int cnt[HID];
    __shared__ int cp[HID + 1];

    const int tid  = threadIdx.x;
    const int w    = tid >> 5;
    const int lane = tid & 31;
    const unsigned FULL = 0xffffffffu;

    // zero-fill entry arrays so padding slots are (r=0, v=0)
    {
        int4 z = make_int4(0, 0, 0, 0);
        for (int i = tid; i < 4096; i += 1024) g_e1[i] = z;
        for (int i = tid; i < 1024; i += 1024) g_e2[i] = z;
    }
    __syncthreads();

    for (int phase = 0; phase < 2; ++phase) {
        const int*   idx = phase ? idx2 : idx1;
        const float* val = phase ? val2 : val1;
        const int    nnz = phase ? nnz2 : nnz1;
        int*  gcp = phase ? g_cp2 : g_cp1;
        int2* ge  = phase ? reinterpret_cast<int2*>(g_e2) : reinterpret_cast<int2*>(g_e1);
        const int* rows = idx;          // idx layout: [2, nnz] (rows then cols)
        const int* cols = idx + nnz;

        // ---- count entries per column (warp w owns cols 2w, 2w+1) ----
        #pragma unroll
        for (int jc = 0; jc < 2; ++jc) {
            const int c = w * 2 + jc;
            int cc = 0;
            for (int ib = 0; ib < nnz; ib += 32) {
                const int i = ib + lane;
                if (i < nnz && cols[i] == c) cc++;
            }
            #pragma unroll
            for (int o = 16; o; o >>= 1) cc += __shfl_xor_sync(FULL, cc, o);
            if (lane == 0) cnt[c] = cc;
        }
        __syncthreads();

        // ---- exclusive scan of counts padded to multiples of 8 ----
        if (tid == 0) {
            int acc = 0;
            for (int c = 0; c < HID; ++c) { cp[c] = acc; acc += (cnt[c] + 7) & ~7; }
            cp[HID] = acc;
        }
        __syncthreads();
        if (tid <= HID) gcp[tid] = cp[tid];

        // ---- deterministic scatter in original index order ----
        #pragma unroll
        for (int jc = 0; jc < 2; ++jc) {
            const int c = w * 2 + jc;
            const int base = cp[c];
            int run = 0;
            for (int ib = 0; ib < nnz; ib += 32) {
                const int i = ib + lane;
                const bool m = (i < nnz) && (cols[i] == c);
                const unsigned mk = __ballot_sync(FULL, m);
                if (m) {
                    const int pos = base + run + __popc(mk & ((1u << lane) - 1u));
                    ge[pos] = make_int2(rows[i], __float_as_int(val[i]));
                }
                run += __popc(mk);
            }
        }
        __syncthreads();
    }

    // ---- densify W3 (single output column; idx3[0..nnz3) are hid rows) ----
    if (tid < HID) {
        float s = 0.f;
        for (int i = 0; i < nnz3; ++i)
            if (idx3[i] == tid) s += val3[i];
        g_w3[tid] = s;
    }
}

// ---------------------------------------------------------------------------
// Main fused kernel: 32 batch rows per block, 16 warps, warp owns 4 columns.
// Entry loop unrolled 4x (4 independent int4 chains = 4 LDG.128 + 8 LDS in
// flight) into 4 independent accumulators; columns padded so there's no tail.
// Smem for h1/h2 aliases the x tile (dead after layer 1) -> 98.4 KB/block
// -> 2 blocks/SM -> 32 warps/SM.
// ---------------------------------------------------------------------------
extern __shared__ float smem[];

__global__ __launch_bounds__(THREADS, 2)
void mlp_kernel(const float* __restrict__ x,
                const float* __restrict__ b1,
                const float* __restrict__ b2,
                const float* __restrict__ b3,
                float* __restrict__ out, int batch)
{
    float* xs  = smem;                         // [32][769]
    float* h1s = smem;                         // reuse (xs dead after layer 1)
    float* h2s = smem + ROWS * HS_STRIDE;      // disjoint from h1s

    const int tid  = threadIdx.x;
    const int w    = tid >> 5;
    const int lane = tid & 31;
    const int row0 = blockIdx.x * ROWS;

    // ---- stage x tile: consecutive threads load/store consecutive words ----
    {
        const float* xg = x + (long long)row0 * IN_F;
        const int totw = min(ROWS, batch - row0) * IN_F;
        #pragma unroll 8
        for (int k = tid; k < ROWS * IN_F; k += THREADS) {
            const int r = k / IN_F;
            const int c = k - r * IN_F;
            xs[r * XS_STRIDE + c] = (k < totw) ? __ldg(&xg[k]) : 0.f;
        }
    }
    __syncthreads();

    // ---- layer 1 ----
    float h[COLS_PER_WARP];
    {
        const float* xr = xs + lane * XS_STRIDE;
        const int4* __restrict__ ge = g_e1;
        #pragma unroll
        for (int j = 0; j < COLS_PER_WARP; ++j) {
            const int c  = w * COLS_PER_WARP + j;
            const int p0 = g_cp1[c] >> 1;          // int4 index
            const int p1 = g_cp1[c + 1] >> 1;      // (p1-p0) % 4 == 0
            float a0 = 0.f, a1 = 0.f, a2 = 0.f, a3 = 0.f;
            for (int p = p0; p < p1; p += 4) {
                const int4 q0 = __ldg(ge + p + 0);
                const int4 q1 = __ldg(ge + p + 1);
                const int4 q2 = __ldg(ge + p + 2);
                const int4 q3 = __ldg(ge + p + 3);
                a0 += xr[q0.x] * __int_as_float(q0.y);
                a1 += xr[q1.x] * __int_as_float(q1.y);
                a2 += xr[q2.x] * __int_as_float(q2.y);
                a3 += xr[q3.x] * __int_as_float(q3.y);
                a0 += xr[q0.z] * __int_as_float(q0.w);
                a1 += xr[q1.z] * __int_as_float(q1.w);
                a2 += xr[q2.z] * __int_as_float(q2.w);
                a3 += xr[q3.z] * __int_as_float(q3.w);
            }
            h[j] = fmaxf((a0 + a1) + (a2 + a3) + __ldg(&b1[c]), 0.f);
        }
    }
    __syncthreads();                               // all warps done reading xs
    #pragma unroll
    for (int j = 0; j < COLS_PER_WARP; ++j)
        h1s[lane * HS_STRIDE + w * COLS_PER_WARP + j] = h[j];
    __syncthreads();

    // ---- layer 2 ----
    {
        const float* hr = h1s + lane * HS_STRIDE;
        const int4* __restrict__ ge = g_e2;
        #pragma unroll
        for (int j = 0; j < COLS_PER_WARP; ++j) {
            const int c  = w * COLS_PER_WARP + j;
            const int p0 = g_cp2[c] >> 1;
            const int p1 = g_cp2[c + 1] >> 1;
            float a0 = 0.f, a1 = 0.f, a2 = 0.f, a3 = 0.f;
            for (int p = p0; p < p1; p += 4) {
                const int4 q0 = __ldg(ge + p + 0);
                const int4 q1 = __ldg(ge + p + 1);
                const int4 q2 = __ldg(ge + p + 2);
                const int4 q3 = __ldg(ge + p + 3);
                a0 += hr[q0.x] * __int_as_float(q0.y);
                a1 += hr[q1.x] * __int_as_float(q1.y);
                a2 += hr[q2.x] * __int_as_float(q2.y);
                a3 += hr[q3.x] * __int_as_float(q3.y);
                a0 += hr[q0.z] * __int_as_float(q0.w);
                a1 += hr[q1.z] * __int_as_float(q1.w);
                a2 += hr[q2.z] * __int_as_float(q2.w);
                a3 += hr[q3.z] * __int_as_float(q3.w);
            }
            h[j] = fmaxf((a0 + a1) + (a2 + a3) + __ldg(&b2[c]), 0.f);
        }
    }
    __syncthreads();
    #pragma unroll
    for (int j = 0; j < COLS_PER_WARP; ++j)
        h2s[lane * HS_STRIDE + w * COLS_PER_WARP + j] = h[j];
    __syncthreads();

    // ---- layer 3: warp 0, lane = row ----
    if (w == 0) {
        const float* hr = h2s + lane * HS_STRIDE;
        float acc = __ldg(&b3[0]);
        #pragma unroll
        for (int c = 0; c < HID; ++c) acc += hr[c] * g_w3[c];
        const int gr = row0 + lane;
        if (gr < batch) out[gr] = acc;
    }
}

// ---------------------------------------------------------------------------
extern "C" void kernel_launch(void* const* d_in, const int* in_sizes, int n_in,
                              void* d_out, int out_size)
{
    const float* x    = (const float*)d_in[0];
    const int*   idx1 = (const int*)  d_in[1];
    const float* val1 = (const float*)d_in[2];
    const float* b1   = (const float*)d_in[3];
    const int*   idx2 = (const int*)  d_in[4];
    const float* val2 = (const float*)d_in[5];
    const float* b2   = (const float*)d_in[6];
    const int*   idx3 = (const int*)  d_in[7];
    const float* val3 = (const float*)d_in[8];
    const float* b3   = (const float*)d_in[9];

    const int nnz1  = in_sizes[1] / 2;
    const int nnz2  = in_sizes[4] / 2;
    const int nnz3  = in_sizes[7] / 2;
    const int batch = in_sizes[0] / IN_F;

    const int smem_bytes = ROWS * XS_STRIDE * (int)sizeof(float);   // 98432
    cudaFuncSetAttribute(mlp_kernel, cudaFuncAttributeMaxDynamicSharedMemorySize, smem_bytes);

    prep_kernel<<<1, 1024>>>(idx1, val1, nnz1, idx2, val2, nnz2, idx3, val3, nnz3);

    const int blocks = (batch + ROWS - 1) / ROWS;
    mlp_kernel<<<blocks, THREADS, smem_bytes>>>(x, b1, b2, b3, (float*)d_out, batch);
}

// round 3
// speedup vs baseline: 2.7049x; 1.3429x over previous
#include <cuda_runtime.h>
#include <cuda_fp16.h>
#include <stdint.h>

#define IN_F      768
#define HID       64
#define ROWS      64            // batch rows per block
#define RPAIRS    32            // 64 rows as 32 half2 row-pairs (lane = rowpair)
#define THREADS   512           // 16 warps * 4 columns
#define COLS_PER_WARP 4
#define XS_STRIDE 33            // half2 units: bank = (c*33+rp)%32 = (c+rp)%32 -> conflict-free

// Device scratch (no allocations allowed). int4 loads give LDG.128 entry pairs.
__device__ int   g_cp1[HID + 1];
__device__ int   g_cp2[HID + 1];
__device__ int4  g_e1[4096];   // (r,v_bits) int2 entries for W1, 4915 + pad-to-4
__device__ int4  g_e2[1024];   // entries for W2, 409 + pad-to-4
__device__ float g_w3[HID];

// ---------------------------------------------------------------------------
// Preprocess: COO -> CSC per output column, deterministic (original index
// order via ballot-prefix ranks). Column segments padded to multiples of FOUR
// entries (2 int4) with zeros. cols[] staged in smem so the 64 per-column
// scans hit LDS, not global. One block, 1024 threads, 2 columns per warp.
// ---------------------------------------------------------------------------
__global__ void prep_kernel(const int* __restrict__ idx1, const float* __restrict__ val1, int nnz1,
                            const int* __restrict__ idx2, const float* __restrict__ val2, int nnz2,
                            const int* __restrict__ idx3, const float* __restrict__ val3, int nnz3)
{
    __shared__ int scols[5120];
    __shared__ int cnt[HID];
    __shared__ int cp[HID + 1];

    const int tid  = threadIdx.x;
    const int w    = tid >> 5;
    const int lane = tid & 31;
    const unsigned FULL = 0xffffffffu;

    // zero-fill entry arrays so padding slots are (r=0, v=0)
    {
        int4 z = make_int4(0, 0, 0, 0);
        for (int i = tid; i < 4096; i += 1024) g_e1[i] = z;
        if (tid < 1024) g_e2[tid] = z;
    }

    for (int phase = 0; phase < 2; ++phase) {
        const int*   idx = phase ? idx2 : idx1;
        const float* val = phase ? val2 : val1;
        const int    nnz = phase ? nnz2 : nnz1;
        int*  gcp = phase ? g_cp2 : g_cp1;
        int2* ge  = phase ? reinterpret_cast<int2*>(g_e2) : reinterpret_cast<int2*>(g_e1);
        const int* rows = idx;          // idx layout: [2, nnz] (rows then cols)
        const int* cols = idx + nnz;

        // stage cols in smem (coalesced, once)
        __syncthreads();
        for (int i = tid; i < nnz; i += 1024) scols[i] = cols[i];
        __syncthreads();

        // ---- count entries per column (warp w owns cols 2w, 2w+1) ----
        #pragma unroll
        for (int jc = 0; jc < 2; ++jc) {
            const int c = w * 2 + jc;
            int cc = 0;
            for (int ib = 0; ib < nnz; ib += 32) {
                const int i = ib + lane;
                if (i < nnz && scols[i] == c) cc++;
            }
            #pragma unroll
            for (int o = 16; o; o >>= 1) cc += __shfl_xor_sync(FULL, cc, o);
            if (lane == 0) cnt[c] = cc;
        }
        __syncthreads();

        // ---- exclusive scan of counts padded to multiples of 4 ----
        if (tid == 0) {
            int acc = 0;
            for (int c = 0; c < HID; ++c) { cp[c] = acc; acc += (cnt[c] + 3) & ~3; }
            cp[HID] = acc;
        }
        __syncthreads();
        if (tid <= HID) gcp[tid] = cp[tid];

        // ---- deterministic scatter in original index order ----
        #pragma unroll
        for (int jc = 0; jc < 2; ++jc) {
            const int c = w * 2 + jc;
            const int base = cp[c];
            int run = 0;
            for (int ib = 0; ib < nnz; ib += 32) {
                const int i = ib + lane;
                const bool m = (i < nnz) && (scols[i] == c);
                const unsigned mk = __ballot_sync(FULL, m);
                if (m) {
                    const int pos = base + run + __popc(mk & ((1u << lane) - 1u));
                    ge[pos] = make_int2(rows[i], __float_as_int(val[i]));
                }
                run += __popc(mk);
            }
        }
    }

    // ---- densify W3 (single output column; idx3[0..nnz3) are hid rows) ----
    if (tid < HID) {
        float s = 0.f;
        for (int i = 0; i < nnz3; ++i)
            if (idx3[i] == tid) s += val3[i];
        g_w3[tid] = s;
    }
}

// ---------------------------------------------------------------------------
// Main fused kernel: 64 batch rows per block, 16 warps, warp owns 4 columns.
// x staged as half2 over row-pairs: xs[feature][rowpair] -> one 128B LDS
// wavefront serves 64 rows. Entry loop reads 2 int4 (4 entries) per iter into
// 4 independent lo/hi accumulator pairs. h1/h2 (half2) alias the dead x tile.
// Smem 101376 B/block -> 2 blocks/SM -> 32 warps/SM.
// ---------------------------------------------------------------------------
extern __shared__ __align__(16) char smem_raw[];

__global__ __launch_bounds__(THREADS, 2)
void mlp_kernel(const float* __restrict__ x,
                const float* __restrict__ b1,
                const float* __restrict__ b2,
                const float* __restrict__ b3,
                float* __restrict__ out, int batch)
{
    __half2* xs  = reinterpret_cast<__half2*>(smem_raw);           // [768][33]
    __half2* h1s = reinterpret_cast<__half2*>(smem_raw);           // reuse (xs dead)
    __half2* h2s = h1s + HID * XS_STRIDE;                          // disjoint

    const int tid  = threadIdx.x;
    const int w    = tid >> 5;
    const int lane = tid & 31;
    const int row0 = blockIdx.x * ROWS;
    const int rowsLeft = batch - row0;

    // ---- stage x tile as half2 row-pairs (coalesced global, conflict-free STS) ----
    {
        const float* xg = x + (size_t)row0 * IN_F;
        #pragma unroll 4
        for (int k = tid; k < RPAIRS * IN_F; k += THREADS) {
            const int rp = k / IN_F;
            const int c  = k - rp * IN_F;
            const int r0i = 2 * rp;
            float a = (r0i     < rowsLeft) ? __ldg(xg + (size_t)r0i * IN_F + c)       : 0.f;
            float b = (r0i + 1 < rowsLeft) ? __ldg(xg + (size_t)(r0i + 1) * IN_F + c) : 0.f;
            xs[c * XS_STRIDE + rp] = __floats2half2_rn(a, b);
        }
    }
    __syncthreads();

    float rl[COLS_PER_WARP], rh[COLS_PER_WARP];

    // ---- layer 1 ----
    {
        const int4* __restrict__ ge = g_e1;
        #pragma unroll
        for (int j = 0; j < COLS_PER_WARP; ++j) {
            const int c  = w * COLS_PER_WARP + j;
            const int p0 = g_cp1[c] >> 1;          // int4 index
            const int p1 = g_cp1[c + 1] >> 1;      // (p1-p0) % 2 == 0
            float l0 = 0.f, h0 = 0.f, l1 = 0.f, h1 = 0.f;
            float l2 = 0.f, h2 = 0.f, l3 = 0.f, h3 = 0.f;
            for (int p = p0; p < p1; p += 2) {
                const int4 qa = __ldg(ge + p);
                const int4 qb = __ldg(ge + p + 1);
                float2 f0 = __half22float2(xs[qa.x * XS_STRIDE + lane]);
                float2 f1 = __half22float2(xs[qa.z * XS_STRIDE + lane]);
                float2 f2 = __half22float2(xs[qb.x * XS_STRIDE + lane]);
                float2 f3 = __half22float2(xs[qb.z * XS_STRIDE + lane]);
                const float v0 = __int_as_float(qa.y);
                const float v1 = __int_as_float(qa.w);
                const float v2 = __int_as_float(qb.y);
                const float v3 = __int_as_float(qb.w);
                l0 += f0.x * v0;  h0 += f0.y * v0;
                l1 += f1.x * v1;  h1 += f1.y * v1;
                l2 += f2.x * v2;  h2 += f2.y * v2;
                l3 += f3.x * v3;  h3 += f3.y * v3;
            }
            const float bb = __ldg(&b1[c]);
            rl[j] = fmaxf((l0 + l1) + (l2 + l3) + bb, 0.f);
            rh[j] = fmaxf((h0 + h1) + (h2 + h3) + bb, 0.f);
        }
    }
    __syncthreads();                               // all warps done reading xs
    #pragma unroll
    for (int j = 0; j < COLS_PER_WARP; ++j)
        h1s[(w * COLS_PER_WARP + j) * XS_STRIDE + lane] = __floats2half2_rn(rl[j], rh[j]);
    __syncthreads();

    // ---- layer 2 ----
    {
        const int4* __restrict__ ge = g_e2;
        #pragma unroll
        for (int j = 0; j < COLS_PER_WARP; ++j) {
            const int c  = w * COLS_PER_WARP + j;
            const int p0 = g_cp2[c] >> 1;
            const int p1 = g_cp2[c + 1] >> 1;
            float l0 = 0.f, h0 = 0.f, l1 = 0.f, h1 = 0.f;
            float l2 = 0.f, h2 = 0.f, l3 = 0.f, h3 = 0.f;
            for (int p = p0; p < p1; p += 2) {
                const int4 qa = __ldg(ge + p);
                const int4 qb = __ldg(ge + p + 1);
                float2 f0 = __half22float2(h1s[qa.x * XS_STRIDE + lane]);
                float2 f1 = __half22float2(h1s[qa.z * XS_STRIDE + lane]);
                float2 f2 = __half22float2(h1s[qb.x * XS_STRIDE + lane]);
                float2 f3 = __half22float2(h1s[qb.z * XS_STRIDE + lane]);
                const float v0 = __int_as_float(qa.y);
                const float v1 = __int_as_float(qa.w);
                const float v2 = __int_as_float(qb.y);
                const float v3 = __int_as_float(qb.w);
                l0 += f0.x * v0;  h0 += f0.y * v0;
                l1 += f1.x * v1;  h1 += f1.y * v1;
                l2 += f2.x * v2;  h2 += f2.y * v2;
                l3 += f3.x * v3;  h3 += f3.y * v3;
            }
            const float bb = __ldg(&b2[c]);
            rl[j] = fmaxf((l0 + l1) + (l2 + l3) + bb, 0.f);
            rh[j] = fmaxf((h0 + h1) + (h2 + h3) + bb, 0.f);
        }
    }
    __syncthreads();
    #pragma unroll
    for (int j = 0; j < COLS_PER_WARP; ++j)
        h2s[(w * COLS_PER_WARP + j) * XS_STRIDE + lane] = __floats2half2_rn(rl[j], rh[j]);
    __syncthreads();

    // ---- layer 3: warp 0, lane = rowpair ----
    if (w == 0) {
        const float bb = __ldg(&b3[0]);
        float lo = bb, hi = bb;
        #pragma unroll
        for (int c = 0; c < HID; ++c) {
            const float wv = g_w3[c];
            float2 f = __half22float2(h2s[c * XS_STRIDE + lane]);
            lo += f.x * wv;
            hi += f.y * wv;
        }
        const int gr = row0 + 2 * lane;
        if (gr + 1 < batch) {
            float2 o; o.x = lo; o.y = hi;
            *reinterpret_cast<float2*>(out + gr) = o;
        } else if (gr < batch) {
            out[gr] = lo;
        }
    }
}

// ---------------------------------------------------------------------------
extern "C" void kernel_launch(void* const* d_in, const int* in_sizes, int n_in,
                              void* d_out, int out_size)
{
    const float* x    = (const float*)d_in[0];
    const int*   idx1 = (const int*)  d_in[1];
    const float* val1 = (const float*)d_in[2];
    const float* b1   = (const float*)d_in[3];
    const int*   idx2 = (const int*)  d_in[4];
    const float* val2 = (const float*)d_in[5];
    const float* b2   = (const float*)d_in[6];
    const int*   idx3 = (const int*)  d_in[7];
    const float* val3 = (const float*)d_in[8];
    const float* b3   = (const float*)d_in[9];

    const int nnz1  = in_sizes[1] / 2;
    const int nnz2  = in_sizes[4] / 2;
    const int nnz3  = in_sizes[7] / 2;
    const int batch = in_sizes[0] / IN_F;

    const int smem_bytes = IN_F * XS_STRIDE * (int)sizeof(__half2);   // 101376
    cudaFuncSetAttribute(mlp_kernel, cudaFuncAttributeMaxDynamicSharedMemorySize, smem_bytes);

    prep_kernel<<<1, 1024>>>(idx1, val1, nnz1, idx2, val2, nnz2, idx3, val3, nnz3);

    const int blocks = (batch + ROWS - 1) / ROWS;
    mlp_kernel<<<blocks, THREADS, smem_bytes>>>(x, b1, b2, b3, (float*)d_out, batch);
}

// round 5
// speedup vs baseline: 3.4460x; 1.2740x over previous
#include <cuda_runtime.h>
#include <cuda_fp16.h>
#include <stdint.h>

#define IN_F    768
#define HID     64
#define MTILE   128
#define KC      64           // K per chunk
#define NCHUNK  12
#define THREADS 256
#define NSTEP1  48           // 768/16 k-steps for layer 1
#define NSTEP2  4            // 64/16 for layer 2

// ---------------- device scratch (no allocations allowed) ----------------
__device__ float g_w1d[HID * IN_F];            // dense W1^T [n][k]
__device__ float g_w2d[HID * HID];             // dense W2^T [n][k]
__device__ uint4 g_w1f[NSTEP1 * 8 * 32];       // B-fragments: (main b0,b1, resid b0,b1)
__device__ uint4 g_w2f[NSTEP2 * 8 * 32];
__device__ float g_w3[HID];

__device__ __forceinline__ uint32_t sw128(uint32_t a) { return a ^ ((a >> 3) & 0x70u); }

static __device__ __forceinline__ void mma16816(float* d, const uint32_t* a,
                                                uint32_t b0, uint32_t b1) {
    asm volatile(
        "mma.sync.aligned.m16n8k16.row.col.f32.f16.f16.f32 "
        "{%0,%1,%2,%3}, {%4,%5,%6,%7}, {%8,%9}, {%0,%1,%2,%3};"
        : "+f"(d[0]), "+f"(d[1]), "+f"(d[2]), "+f"(d[3])
        : "r"(a[0]), "r"(a[1]), "r"(a[2]), "r"(a[3]), "r"(b0), "r"(b1));
}
static __device__ __forceinline__ void ldmx4(uint32_t* a, uint32_t addr) {
    asm volatile("ldmatrix.sync.aligned.m8n8.x4.shared.b16 {%0,%1,%2,%3}, [%4];"
                 : "=r"(a[0]), "=r"(a[1]), "=r"(a[2]), "=r"(a[3]) : "r"(addr));
}
static __device__ __forceinline__ uint32_t pkh(__half a, __half b) {
    __half2 h = __halves2half2(a, b);
    return *reinterpret_cast<uint32_t*>(&h);
}

// ---------------- prep: zero -> scatter -> pack fragments ----------------
__global__ void zero_kernel() {
    const int t = blockIdx.x * blockDim.x + threadIdx.x;
    const int n = gridDim.x * blockDim.x;
    for (int i = t; i < HID * IN_F; i += n) g_w1d[i] = 0.f;
    for (int i = t; i < HID * HID;  i += n) g_w2d[i] = 0.f;
    for (int i = t; i < HID;        i += n) g_w3[i]  = 0.f;
}

__global__ void scatter_kernel(const int* __restrict__ idx1, const float* __restrict__ val1, int nnz1,
                               const int* __restrict__ idx2, const float* __restrict__ val2, int nnz2,
                               const int* __restrict__ idx3, const float* __restrict__ val3, int nnz3)
{
    const int t = blockIdx.x * blockDim.x + threadIdx.x;
    const int n = gridDim.x * blockDim.x;
    // idx layout [2,nnz]: rows then cols. dense is [n(col)][k(row)].
    for (int i = t; i < nnz1; i += n)
        atomicAdd(&g_w1d[idx1[nnz1 + i] * IN_F + idx1[i]], val1[i]);
    for (int i = t; i < nnz2; i += n)
        atomicAdd(&g_w2d[idx2[nnz2 + i] * HID + idx2[i]], val2[i]);
    for (int i = t; i < nnz3; i += n)
        atomicAdd(&g_w3[idx3[i]], val3[i]);
}

__global__ void pack_kernel() {
    const int tid = threadIdx.x;
    if (blockIdx.x < NSTEP1) {                 // one block per k-step of W1
        const int s    = blockIdx.x;
        const int nb   = tid >> 5;
        const int lane = tid & 31;
        const int k0 = s * 16 + (lane & 3) * 2;
        const int n  = nb * 8 + (lane >> 2);
        const float m0 = g_w1d[n * IN_F + k0];
        const float m1 = g_w1d[n * IN_F + k0 + 1];
        const float m2 = g_w1d[n * IN_F + k0 + 8];
        const float m3 = g_w1d[n * IN_F + k0 + 9];
        const __half h0 = __float2half_rn(m0), h1 = __float2half_rn(m1);
        const __half h2 = __float2half_rn(m2), h3 = __float2half_rn(m3);
        uint4 u;
        u.x = pkh(h0, h1);
        u.y = pkh(h2, h3);
        u.z = pkh(__float2half_rn(m0 - __half2float(h0)), __float2half_rn(m1 - __half2float(h1)));
        u.w = pkh(__float2half_rn(m2 - __half2float(h2)), __float2half_rn(m3 - __half2float(h3)));
        g_w1f[(s * 8 + nb) * 32 + lane] = u;
    } else {                                   // last block packs all of W2
        for (int j = tid; j < NSTEP2 * 8 * 32; j += THREADS) {
            const int s    = j >> 8;
            const int nb   = (j >> 5) & 7;
            const int lane = j & 31;
            const int k0 = s * 16 + (lane & 3) * 2;
            const int n  = nb * 8 + (lane >> 2);
            const float m0 = g_w2d[n * HID + k0];
            const float m1 = g_w2d[n * HID + k0 + 1];
            const float m2 = g_w2d[n * HID + k0 + 8];
            const float m3 = g_w2d[n * HID + k0 + 9];
            const __half h0 = __float2half_rn(m0), h1 = __float2half_rn(m1);
            const __half h2 = __float2half_rn(m2), h3 = __float2half_rn(m3);
            uint4 u;
            u.x = pkh(h0, h1);
            u.y = pkh(h2, h3);
            u.z = pkh(__float2half_rn(m0 - __half2float(h0)), __float2half_rn(m1 - __half2float(h1)));
            u.w = pkh(__float2half_rn(m2 - __half2float(h2)), __float2half_rn(m3 - __half2float(h3)));
            g_w2f[(s * 8 + nb) * 32 + lane] = u;
        }
    }
}

// ---------------- smem layout (bytes) ----------------
#define SM_B1   0
#define SM_B2   256
#define SM_W3   512
#define SM_X    1024                  // 2 x 16384 (x chunk, fp16 SW128, 128 rows x 128B)
#define SM_H1   33792                 // 16384     (h1 fp16 SW128)
#define SMEM_TOTAL 50176

extern __shared__ unsigned char smem[];

__global__ __launch_bounds__(THREADS, 2)
void mma_kernel(const float* __restrict__ x,
                const float* __restrict__ b1,
                const float* __restrict__ b2,
                const float* __restrict__ b3,
                float* __restrict__ out, int batch)
{
    uint32_t sb;
    asm("{ .reg .u64 t; cvta.to.shared.u64 t, %1; cvt.u32.u64 %0, t; }" : "=r"(sb) : "l"(smem));
    const int tid  = threadIdx.x;
    const int w    = tid >> 5;
    const int lane = tid & 31;
    const int row0 = blockIdx.x * MTILE;

    if (tid < HID) {
        ((float*)(smem + SM_B1))[tid] = __ldg(b1 + tid);
        ((float*)(smem + SM_B2))[tid] = __ldg(b2 + tid);
        ((float*)(smem + SM_W3))[tid] = g_w3[tid];
    }

    // staging geometry: thread -> (row, half-row of 32 f32)
    const int srow  = tid >> 1;
    const int shalf = tid & 1;
    const bool rok  = (row0 + srow) < batch;
    const float4* xf4 = reinterpret_cast<const float4*>(x) +
                        ((size_t)(row0 + srow) * (IN_F / 4) + shalf * 8);
    const uint32_t sbase = srow * 128 + shalf * 64;

    // ldmatrix A-address component (fixed per thread)
    const uint32_t abase = (16 * w + (lane & 15)) * 128 + (lane >> 4) * 16;

    float acc[32];
    #pragma unroll
    for (int i = 0; i < 32; ++i) acc[i] = 0.f;

    // ---- stage chunk 0 ----
    #pragma unroll
    for (int i = 0; i < 4; ++i) {
        float4 v0 = rok ? __ldg(xf4 + 2 * i)     : make_float4(0.f, 0.f, 0.f, 0.f);
        float4 v1 = rok ? __ldg(xf4 + 2 * i + 1) : make_float4(0.f, 0.f, 0.f, 0.f);
        uint4 u;
        u.x = pkh(__float2half_rn(v0.x), __float2half_rn(v0.y));
        u.y = pkh(__float2half_rn(v0.z), __float2half_rn(v0.w));
        u.z = pkh(__float2half_rn(v1.x), __float2half_rn(v1.y));
        u.w = pkh(__float2half_rn(v1.z), __float2half_rn(v1.w));
        *(uint4*)(smem + SM_X + sw128(sbase + i * 16)) = u;
    }
    __syncthreads();

    // ---- mainloop: layer-1 GEMM ----
    for (int k = 0; k < NCHUNK; ++k) {
        const int p = k & 1;
        if (k < NCHUNK - 1) {          // stage next chunk into other buffer
            const float4* src = xf4 + (size_t)(k + 1) * 16;
            unsigned char* dst = smem + SM_X + (p ^ 1) * 16384;
            #pragma unroll
            for (int i = 0; i < 4; ++i) {
                float4 v0 = rok ? __ldg(src + 2 * i)     : make_float4(0.f, 0.f, 0.f, 0.f);
                float4 v1 = rok ? __ldg(src + 2 * i + 1) : make_float4(0.f, 0.f, 0.f, 0.f);
                uint4 u;
                u.x = pkh(__float2half_rn(v0.x), __float2half_rn(v0.y));
                u.y = pkh(__float2half_rn(v0.z), __float2half_rn(v0.w));
                u.z = pkh(__float2half_rn(v1.x), __float2half_rn(v1.y));
                u.w = pkh(__float2half_rn(v1.z), __float2half_rn(v1.w));
                *(uint4*)(dst + sw128(sbase + i * 16)) = u;
            }
        }
        // compute chunk k
        #pragma unroll
        for (int s = 0; s < 4; ++s) {
            uint32_t a[4];
            ldmx4(a, sb + SM_X + p * 16384 + sw128(abase + s * 32));
            const int sg = k * 4 + s;
            const uint4* wf = g_w1f + (size_t)sg * 256 + lane;
            #pragma unroll
            for (int nb = 0; nb < 8; ++nb) {
                const uint4 f = __ldg(wf + nb * 32);
                mma16816(acc + nb * 4, a, f.x, f.y);
                mma16816(acc + nb * 4, a, f.z, f.w);
            }
        }
        __syncthreads();
    }

    // ---- epilogue 1: h1 = relu(acc + b1) -> fp16 SW128 smem ----
    {
        const float* b1s = (const float*)(smem + SM_B1);
        const int rA = 16 * w + (lane >> 2);
        const uint32_t cofs = (lane & 3) * 4;
        #pragma unroll
        for (int nb = 0; nb < 8; ++nb) {
            const int n = nb * 8 + (lane & 3) * 2;
            const float ba = b1s[n], bb = b1s[n + 1];
            const float v0 = fmaxf(acc[nb * 4 + 0] + ba, 0.f);
            const float v1 = fmaxf(acc[nb * 4 + 1] + bb, 0.f);
            const float v2 = fmaxf(acc[nb * 4 + 2] + ba, 0.f);
            const float v3 = fmaxf(acc[nb * 4 + 3] + bb, 0.f);
            *(uint32_t*)(smem + SM_H1 + sw128((uint32_t)(rA * 128)       + nb * 16 + cofs)) =
                pkh(__float2half_rn(v0), __float2half_rn(v1));
            *(uint32_t*)(smem + SM_H1 + sw128((uint32_t)((rA + 8) * 128) + nb * 16 + cofs)) =
                pkh(__float2half_rn(v2), __float2half_rn(v3));
        }
    }
    __syncthreads();

    // ---- layer-2 GEMM (K=64) ----
    float ac2[32];
    #pragma unroll
    for (int i = 0; i < 32; ++i) ac2[i] = 0.f;
    #pragma unroll
    for (int s = 0; s < 4; ++s) {
        uint32_t a[4];
        ldmx4(a, sb + SM_H1 + sw128(abase + s * 32));
        const uint4* wf = g_w2f + (size_t)s * 256 + lane;
        #pragma unroll
        for (int nb = 0; nb < 8; ++nb) {
            const uint4 f = __ldg(wf + nb * 32);
            mma16816(ac2 + nb * 4, a, f.x, f.y);
            mma16816(ac2 + nb * 4, a, f.z, f.w);
        }
    }

    // ---- epilogue 2: out = relu(ac2 + b2) . w3 + b3 ----
    {
        const float* b2s = (const float*)(smem + SM_B2);
        const float* w3s = (const float*)(smem + SM_W3);
        float pA = 0.f, pB = 0.f;
        #pragma unroll
        for (int nb = 0; nb < 8; ++nb) {
            const int n = nb * 8 + (lane & 3) * 2;
            const float ba = b2s[n],  bb = b2s[n + 1];
            const float wa = w3s[n],  wb = w3s[n + 1];
            pA += fmaxf(ac2[nb * 4 + 0] + ba, 0.f) * wa
                + fmaxf(ac2[nb * 4 + 1] + bb, 0.f) * wb;
            pB += fmaxf(ac2[nb * 4 + 2] + ba, 0.f) * wa
                + fmaxf(ac2[nb * 4 + 3] + bb, 0.f) * wb;
        }
        pA += __shfl_xor_sync(0xffffffffu, pA, 1);
        pA += __shfl_xor_sync(0xffffffffu, pA, 2);
        pB += __shfl_xor_sync(0xffffffffu, pB, 1);
        pB += __shfl_xor_sync(0xffffffffu, pB, 2);
        if ((lane & 3) == 0) {
            const float b3v = __ldg(b3);
            const int rA = row0 + 16 * w + (lane >> 2);
            if (rA < batch)     out[rA]     = pA + b3v;
            if (rA + 8 < batch) out[rA + 8] = pB + b3v;
        }
    }
}

// ---------------------------------------------------------------------------
extern "C" void kernel_launch(void* const* d_in, const int* in_sizes, int n_in,
                              void* d_out, int out_size)
{
    const float* x    = (const float*)d_in[0];
    const int*   idx1 = (const int*)  d_in[1];
    const float* val1 = (const float*)d_in[2];
    const float* b1   = (const float*)d_in[3];
    const int*   idx2 = (const int*)  d_in[4];
    const float* val2 = (const float*)d_in[5];
    const float* b2   = (const float*)d_in[6];
    const int*   idx3 = (const int*)  d_in[7];
    const float* val3 = (const float*)d_in[8];
    const float* b3   = (const float*)d_in[9];

    const int nnz1  = in_sizes[1] / 2;
    const int nnz2  = in_sizes[4] / 2;
    const int nnz3  = in_sizes[7] / 2;
    const int batch = in_sizes[0] / IN_F;

    cudaFuncSetAttribute(mma_kernel, cudaFuncAttributeMaxDynamicSharedMemorySize, SMEM_TOTAL);

    zero_kernel<<<64, 256>>>();
    scatter_kernel<<<32, 256>>>(idx1, val1, nnz1, idx2, val2, nnz2, idx3, val3, nnz3);
    pack_kernel<<<NSTEP1 + 1, THREADS>>>();

    const int blocks = (batch + MTILE - 1) / MTILE;
    mma_kernel<<<blocks, THREADS, SMEM_TOTAL>>>(x, b1, b2, b3, (float*)d_out, batch);
}

// round 6
// speedup vs baseline: 4.9360x; 1.4324x over previous
#include <cuda_runtime.h>
#include <cuda_fp16.h>
#include <stdint.h>

#define IN_F    768
#define HID     64
#define MTILE   256
#define NCHUNK  12
#define THREADS 256
#define NSTEP1  48           // 768/16 k-steps for layer 1
#define NSTEP2  4            // 64/16 for layer 2

// ---------------- device scratch (no allocations allowed) ----------------
__device__ float g_w1d[HID * IN_F];            // dense W1^T [n][k]
__device__ float g_w2d[HID * HID];             // dense W2^T [n][k]
__device__ uint4 g_w1f[NSTEP1 * 8 * 32];       // B-fragments: (main b0,b1, resid b0,b1)
__device__ uint4 g_w2f[NSTEP2 * 8 * 32];
__device__ float g_w3[HID];

__device__ __forceinline__ uint32_t sw128(uint32_t a) { return a ^ ((a >> 3) & 0x70u); }

static __device__ __forceinline__ void mma16816(float* d, const uint32_t* a,
                                                uint32_t b0, uint32_t b1) {
    asm volatile(
        "mma.sync.aligned.m16n8k16.row.col.f32.f16.f16.f32 "
        "{%0,%1,%2,%3}, {%4,%5,%6,%7}, {%8,%9}, {%0,%1,%2,%3};"
        : "+f"(d[0]), "+f"(d[1]), "+f"(d[2]), "+f"(d[3])
        : "r"(a[0]), "r"(a[1]), "r"(a[2]), "r"(a[3]), "r"(b0), "r"(b1));
}
static __device__ __forceinline__ void ldmx4(uint32_t* a, uint32_t addr) {
    asm volatile("ldmatrix.sync.aligned.m8n8.x4.shared.b16 {%0,%1,%2,%3}, [%4];"
                 : "=r"(a[0]), "=r"(a[1]), "=r"(a[2]), "=r"(a[3]) : "r"(addr));
}
static __device__ __forceinline__ uint32_t pkh(__half a, __half b) {
    __half2 h = __halves2half2(a, b);
    return *reinterpret_cast<uint32_t*>(&h);
}

// ---------------- prep: zero -> scatter -> pack fragments ----------------
__global__ void zero_kernel() {
    const int t = blockIdx.x * blockDim.x + threadIdx.x;
    const int n = gridDim.x * blockDim.x;
    for (int i = t; i < HID * IN_F; i += n) g_w1d[i] = 0.f;
    for (int i = t; i < HID * HID;  i += n) g_w2d[i] = 0.f;
    for (int i = t; i < HID;        i += n) g_w3[i]  = 0.f;
}

__global__ void scatter_kernel(const int* __restrict__ idx1, const float* __restrict__ val1, int nnz1,
                               const int* __restrict__ idx2, const float* __restrict__ val2, int nnz2,
                               const int* __restrict__ idx3, const float* __restrict__ val3, int nnz3)
{
    const int t = blockIdx.x * blockDim.x + threadIdx.x;
    const int n = gridDim.x * blockDim.x;
    // idx layout [2,nnz]: rows then cols. dense is [n(col)][k(row)].
    for (int i = t; i < nnz1; i += n)
        atomicAdd(&g_w1d[idx1[nnz1 + i] * IN_F + idx1[i]], val1[i]);
    for (int i = t; i < nnz2; i += n)
        atomicAdd(&g_w2d[idx2[nnz2 + i] * HID + idx2[i]], val2[i]);
    for (int i = t; i < nnz3; i += n)
        atomicAdd(&g_w3[idx3[i]], val3[i]);
}

__global__ void pack_kernel() {
    const int tid = threadIdx.x;
    if (blockIdx.x < NSTEP1) {                 // one block per k-step of W1
        const int s    = blockIdx.x;
        const int nb   = tid >> 5;
        const int lane = tid & 31;
        const int k0 = s * 16 + (lane & 3) * 2;
        const int n  = nb * 8 + (lane >> 2);
        const float m0 = g_w1d[n * IN_F + k0];
        const float m1 = g_w1d[n * IN_F + k0 + 1];
        const float m2 = g_w1d[n * IN_F + k0 + 8];
        const float m3 = g_w1d[n * IN_F + k0 + 9];
        const __half h0 = __float2half_rn(m0), h1 = __float2half_rn(m1);
        const __half h2 = __float2half_rn(m2), h3 = __float2half_rn(m3);
        uint4 u;
        u.x = pkh(h0, h1);
        u.y = pkh(h2, h3);
        u.z = pkh(__float2half_rn(m0 - __half2float(h0)), __float2half_rn(m1 - __half2float(h1)));
        u.w = pkh(__float2half_rn(m2 - __half2float(h2)), __float2half_rn(m3 - __half2float(h3)));
        g_w1f[(s * 8 + nb) * 32 + lane] = u;
    } else {                                   // last block packs all of W2
        for (int j = tid; j < NSTEP2 * 8 * 32; j += THREADS) {
            const int s    = j >> 8;
            const int nb   = (j >> 5) & 7;
            const int lane = j & 31;
            const int k0 = s * 16 + (lane & 3) * 2;
            const int n  = nb * 8 + (lane >> 2);
            const float m0 = g_w2d[n * HID + k0];
            const float m1 = g_w2d[n * HID + k0 + 1];
            const float m2 = g_w2d[n * HID + k0 + 8];
            const float m3 = g_w2d[n * HID + k0 + 9];
            const __half h0 = __float2half_rn(m0), h1 = __float2half_rn(m1);
            const __half h2 = __float2half_rn(m2), h3 = __float2half_rn(m3);
            uint4 u;
            u.x = pkh(h0, h1);
            u.y = pkh(h2, h3);
            u.z = pkh(__float2half_rn(m0 - __half2float(h0)), __float2half_rn(m1 - __half2float(h1)));
            u.w = pkh(__float2half_rn(m2 - __half2float(h2)), __float2half_rn(m3 - __half2float(h3)));
            g_w2f[(s * 8 + nb) * 32 + lane] = u;
        }
    }
}

// ---------------- smem layout (bytes) ----------------
#define SM_B1   0
#define SM_B2   256
#define SM_W3   512
#define SM_X    1024                  // 2 x 32768 (x chunk: 256 rows x 128B fp16, SW128)
#define SM_H1   66560                 // 32768     (h1: 256 rows x 128B fp16, SW128)
#define SMEM_TOTAL 99328

extern __shared__ unsigned char smem[];

__global__ __launch_bounds__(THREADS, 2)
void mma_kernel(const float* __restrict__ x,
                const float* __restrict__ b1,
                const float* __restrict__ b2,
                const float* __restrict__ b3,
                float* __restrict__ out, int batch)
{
    uint32_t sb;
    asm("{ .reg .u64 t; cvta.to.shared.u64 t, %1; cvt.u32.u64 %0, t; }" : "=r"(sb) : "l"(smem));
    const int tid  = threadIdx.x;
    const int w    = tid >> 5;
    const int lane = tid & 31;
    const int row0 = blockIdx.x * MTILE;
    const bool full = (row0 + MTILE) <= batch;

    if (tid < HID) {
        ((float*)(smem + SM_B1))[tid] = __ldg(b1 + tid);
        ((float*)(smem + SM_B2))[tid] = __ldg(b2 + tid);
        ((float*)(smem + SM_W3))[tid] = g_w3[tid];
    }

    // coalesced staging map: thread -> fixed col4, rows j*16 + (tid>>4)
    const int c4   = tid & 15;
    const int rsub = tid >> 4;

    // ldmatrix A-address bases for the warp's two 16-row stripes
    const uint32_t ab0 = (uint32_t)((      w * 16 + (lane & 15)) * 128 + (lane >> 4) * 16);
    const uint32_t ab1 = (uint32_t)((128 + w * 16 + (lane & 15)) * 128 + (lane >> 4) * 16);

    float acc0[32], acc1[32];
    #pragma unroll
    for (int i = 0; i < 32; ++i) { acc0[i] = 0.f; acc1[i] = 0.f; }

    // ---- stage one 64-K chunk (coalesced LDG.128, swizzled STS.64) ----
    auto stage = [&](int k, int p) {
        unsigned char* dst = smem + SM_X + p * 32768;
        #pragma unroll 4
        for (int j = 0; j < 16; ++j) {
            const int row = j * 16 + rsub;
            const bool ok = full || (row0 + row) < batch;
            float4 v = make_float4(0.f, 0.f, 0.f, 0.f);
            if (ok)
                v = __ldg(reinterpret_cast<const float4*>(x) +
                          ((size_t)(row0 + row) * (IN_F / 4) + k * 16 + c4));
            uint2 u;
            u.x = pkh(__float2half_rn(v.x), __float2half_rn(v.y));
            u.y = pkh(__float2half_rn(v.z), __float2half_rn(v.w));
            *(uint2*)(dst + sw128((uint32_t)(row * 128 + c4 * 8))) = u;
        }
    };

    stage(0, 0);
    __syncthreads();

    // ---- mainloop: layer-1 GEMM over 12 chunks ----
    for (int k = 0; k < NCHUNK; ++k) {
        const int p = k & 1;
        if (k < NCHUNK - 1) stage(k + 1, p ^ 1);

        const uint32_t xb = sb + SM_X + p * 32768;
        #pragma unroll
        for (int s = 0; s < 4; ++s) {
            uint32_t a0[4], a1[4];
            ldmx4(a0, xb + sw128(ab0 + s * 32));
            ldmx4(a1, xb + sw128(ab1 + s * 32));
            const uint4* wf = g_w1f + (size_t)(k * 4 + s) * 256 + lane;
            #pragma unroll
            for (int nb = 0; nb < 8; ++nb) {
                const uint4 f = __ldg(wf + nb * 32);
                mma16816(acc0 + nb * 4, a0, f.x, f.y);
                mma16816(acc0 + nb * 4, a0, f.z, f.w);
                mma16816(acc1 + nb * 4, a1, f.x, f.y);
                mma16816(acc1 + nb * 4, a1, f.z, f.w);
            }
        }
        __syncthreads();
    }

    // ---- epilogue 1: h1 = relu(acc + b1) -> fp16 SW128 smem (both stripes) ----
    {
        const float* b1s = (const float*)(smem + SM_B1);
        const int r = lane >> 2;
        const uint32_t cofs = (lane & 3) * 4;
        #pragma unroll
        for (int st = 0; st < 2; ++st) {
            const float* ac = st ? acc1 : acc0;
            const int R = st * 128 + w * 16 + r;
            #pragma unroll
            for (int nb = 0; nb < 8; ++nb) {
                const int n = nb * 8 + (lane & 3) * 2;
                const float ba = b1s[n], bb = b1s[n + 1];
                const float v0 = fmaxf(ac[nb * 4 + 0] + ba, 0.f);
                const float v1 = fmaxf(ac[nb * 4 + 1] + bb, 0.f);
                const float v2 = fmaxf(ac[nb * 4 + 2] + ba, 0.f);
                const float v3 = fmaxf(ac[nb * 4 + 3] + bb, 0.f);
                *(uint32_t*)(smem + SM_H1 + sw128((uint32_t)(R * 128)       + nb * 16 + cofs)) =
                    pkh(__float2half_rn(v0), __float2half_rn(v1));
                *(uint32_t*)(smem + SM_H1 + sw128((uint32_t)((R + 8) * 128) + nb * 16 + cofs)) =
                    pkh(__float2half_rn(v2), __float2half_rn(v3));
            }
        }
    }
    __syncthreads();

    // ---- layer-2 GEMM (K=64) ----
    float ac20[32], ac21[32];
    #pragma unroll
    for (int i = 0; i < 32; ++i) { ac20[i] = 0.f; ac21[i] = 0.f; }
    #pragma unroll
    for (int s = 0; s < 4; ++s) {
        uint32_t a0[4], a1[4];
        ldmx4(a0, sb + SM_H1 + sw128(ab0 + s * 32));
        ldmx4(a1, sb + SM_H1 + sw128(ab1 + s * 32));
        const uint4* wf = g_w2f + (size_t)s * 256 + lane;
        #pragma unroll
        for (int nb = 0; nb < 8; ++nb) {
            const uint4 f = __ldg(wf + nb * 32);
            mma16816(ac20 + nb * 4, a0, f.x, f.y);
            mma16816(ac20 + nb * 4, a0, f.z, f.w);
            mma16816(ac21 + nb * 4, a1, f.x, f.y);
            mma16816(ac21 + nb * 4, a1, f.z, f.w);
        }
    }

    // ---- epilogue 2: out = relu(ac2 + b2) . w3 + b3 ----
    {
        const float* b2s = (const float*)(smem + SM_B2);
        const float* w3s = (const float*)(smem + SM_W3);
        const float b3v = __ldg(b3);
        #pragma unroll
        for (int st = 0; st < 2; ++st) {
            const float* ac = st ? ac21 : ac20;
            float pA = 0.f, pB = 0.f;
            #pragma unroll
            for (int nb = 0; nb < 8; ++nb) {
                const int n = nb * 8 + (lane & 3) * 2;
                const float ba = b2s[n],  bb = b2s[n + 1];
                const float wa = w3s[n],  wb = w3s[n + 1];
                pA += fmaxf(ac[nb * 4 + 0] + ba, 0.f) * wa
                    + fmaxf(ac[nb * 4 + 1] + bb, 0.f) * wb;
                pB += fmaxf(ac[nb * 4 + 2] + ba, 0.f) * wa
                    + fmaxf(ac[nb * 4 + 3] + bb, 0.f) * wb;
            }
            pA += __shfl_xor_sync(0xffffffffu, pA, 1);
            pA += __shfl_xor_sync(0xffffffffu, pA, 2);
            pB += __shfl_xor_sync(0xffffffffu, pB, 1);
            pB += __shfl_xor_sync(0xffffffffu, pB, 2);
            if ((lane & 3) == 0) {
                const int rA = row0 + st * 128 + w * 16 + (lane >> 2);
                if (rA < batch)     out[rA]     = pA + b3v;
                if (rA + 8 < batch) out[rA + 8] = pB + b3v;
            }
        }
    }
}

// ---------------------------------------------------------------------------
extern "C" void kernel_launch(void* const* d_in, const int* in_sizes, int n_in,
                              void* d_out, int out_size)
{
    const float* x    = (const float*)d_in[0];
    const int*   idx1 = (const int*)  d_in[1];
    const float* val1 = (const float*)d_in[2];
    const float* b1   = (const float*)d_in[3];
    const int*   idx2 = (const int*)  d_in[4];
    const float* val2 = (const float*)d_in[5];
    const float* b2   = (const float*)d_in[6];
    const int*   idx3 = (const int*)  d_in[7];
    const float* val3 = (const float*)d_in[8];
    const float* b3   = (const float*)d_in[9];

    const int nnz1  = in_sizes[1] / 2;
    const int nnz2  = in_sizes[4] / 2;
    const int nnz3  = in_sizes[7] / 2;
    const int batch = in_sizes[0] / IN_F;

    cudaFuncSetAttribute(mma_kernel, cudaFuncAttributeMaxDynamicSharedMemorySize, SMEM_TOTAL);

    zero_kernel<<<64, 256>>>();
    scatter_kernel<<<32, 256>>>(idx1, val1, nnz1, idx2, val2, nnz2, idx3, val3, nnz3);
    pack_kernel<<<NSTEP1 + 1, THREADS>>>();

    const int blocks = (batch + MTILE - 1) / MTILE;
    mma_kernel<<<blocks, THREADS, SMEM_TOTAL>>>(x, b1, b2, b3, (float*)d_out, batch);
}